// round 11
// baseline (speedup 1.0000x reference)
#include <cuda_runtime.h>

#define NN   50000
#define NSEG 150000          // 3 relations x NN segments, v = r*NN + node
#define NT   256
#define EMAX 4500000
#define SCAN_BS 1024

// ---------------- scratch (static device globals; no allocs) ----------------
__device__ int   g_is64;
__device__ int   g_dout[NSEG];           // out-degree per (r,node)
__device__ int   g_din [NSEG];           // in-degree per (r,node)
__device__ int2  g_edges [EMAX];         // compact (src seg, dst seg), unsorted
__device__ int2  g_sorted[EMAX];         // dst-sorted edges (grouped by dst)
__device__ int   g_off [NSEG + 1];       // offsets by dst segment
__device__ int   g_cur [NSEG];           // fill cursors
__device__ int   g_part[256];            // scan block partials
__device__ float g_h1 [NSEG * 16];       // rsqrt(dout)-scaled layer-1 features
__device__ float g_m  [NSEG * 16];       // raw aggregation buffers
__device__ float g_s  [NSEG];            // scalar layer-2 messages
__device__ float g_o2 [NSEG];            // scalar layer-2 accumulators

// ---------------- dtype detection ----------------
__global__ void k_detect(const unsigned* __restrict__ p, int n) {
    __shared__ int found;
    if (threadIdx.x == 0) found = 0;
    __syncthreads();
    int f = 0;
    for (int i = threadIdx.x; i < n; i += blockDim.x)
        if (p[2 * i + 1] != 0u) f = 1;
    if (f) atomicOr(&found, 1);
    __syncthreads();
    if (threadIdx.x == 0) g_is64 = found ? 0 : 1;
}

__device__ __forceinline__ int ldidx(const void* __restrict__ p, int i) {
    return g_is64 ? (int)__ldg((const long long*)p + i)
                  : __ldg((const int*)p + i);
}

__device__ __forceinline__ float rs_of(int cnt) {
    return rsqrtf((float)(cnt > 0 ? cnt : 1));
}

// ---------------- zero counters ----------------
__global__ void k_zero() {
    int i = blockIdx.x * blockDim.x + threadIdx.x;
    if (i < NSEG) { g_dout[i] = 0; g_din[i] = 0; }
}

// ------- degrees + compact int2 edge emit (single pass over raw idx) --------
__global__ void k_degc(const void* __restrict__ src, const void* __restrict__ dst,
                       int E, int r, int eoff) {
    int e = blockIdx.x * blockDim.x + threadIdx.x;
    if (e >= E) return;
    int s = r * NN + ldidx(src, e);
    int d = r * NN + ldidx(dst, e);
    atomicAdd(&g_dout[s], 1);
    atomicAdd(&g_din [d], 1);
    g_edges[eoff + e] = make_int2(s, d);
}

// ---------------- exclusive scan over g_din ----------------
__global__ void k_scan1() {
    __shared__ int ws[32];
    int b = blockIdx.x, t = threadIdx.x;
    int v = b * SCAN_BS + t;
    int val = (v < NSEG) ? g_din[v] : 0;
    #pragma unroll
    for (int o = 16; o; o >>= 1) val += __shfl_down_sync(0xffffffffu, val, o);
    if ((t & 31) == 0) ws[t >> 5] = val;
    __syncthreads();
    if (t < 32) {
        int x = ws[t];
        #pragma unroll
        for (int o = 16; o; o >>= 1) x += __shfl_down_sync(0xffffffffu, x, o);
        if (t == 0) g_part[b] = x;
    }
}

__global__ void k_scan2(int nblk) {
    __shared__ int sh[256];
    int t = threadIdx.x;
    sh[t] = (t < nblk) ? g_part[t] : 0;
    __syncthreads();
    for (int o = 1; o < 256; o <<= 1) {
        int y = (t >= o) ? sh[t - o] : 0;
        __syncthreads();
        sh[t] += y;
        __syncthreads();
    }
    if (t < nblk) g_part[t] = (t == 0) ? 0 : sh[t - 1];
    if (t == 0) g_off[NSEG] = sh[nblk - 1];
}

__global__ void k_scan3() {
    __shared__ int ws[32];
    int b = blockIdx.x, t = threadIdx.x;
    int v = b * SCAN_BS + t;
    int lane = t & 31, wid = t >> 5;
    int val = (v < NSEG) ? g_din[v] : 0;
    int x = val;
    #pragma unroll
    for (int o = 1; o < 32; o <<= 1) {
        int y = __shfl_up_sync(0xffffffffu, x, o);
        if (lane >= o) x += y;
    }
    if (lane == 31) ws[wid] = x;
    __syncthreads();
    if (wid == 0) {
        int w = ws[lane];
        #pragma unroll
        for (int o = 1; o < 32; o <<= 1) {
            int y = __shfl_up_sync(0xffffffffu, w, o);
            if (lane >= o) w += y;
        }
        ws[lane] = w;
    }
    __syncthreads();
    int base = g_part[b] + (wid > 0 ? ws[wid - 1] : 0);
    int excl = base + x - val;
    if (v < NSEG) { g_off[v] = excl; g_cur[v] = excl; }
}

// ---------------- group edges by dst via cursor scatter ----------------
__global__ void k_fill(int Etot) {
    int e = blockIdx.x * blockDim.x + threadIdx.x;
    if (e >= Etot) return;
    int2 ed = __ldg((const int2*)&g_edges[e]);
    int pos = atomicAdd(&g_cur[ed.y], 1);
    g_sorted[pos] = ed;
}

// ---------------- layer 1: per-node transform (and zero g_m) ----------------
__global__ void k_layer1_node(const float* __restrict__ x, const float* __restrict__ W1) {
    __shared__ float sW[3 * 32 * 16];
    for (int i = threadIdx.x; i < 1536; i += blockDim.x) sW[i] = W1[i];
    __syncthreads();
    int n = blockIdx.x * blockDim.x + threadIdx.x;
    if (n >= NN) return;
    float xv[32];
    #pragma unroll
    for (int j = 0; j < 8; j++) {
        float4 v = __ldg((const float4*)(x + (size_t)n * 32) + j);
        xv[4*j] = v.x; xv[4*j+1] = v.y; xv[4*j+2] = v.z; xv[4*j+3] = v.w;
    }
    #pragma unroll
    for (int r = 0; r < 3; r++) {
        float a = rs_of(g_dout[r * NN + n]);
        float y[16];
        #pragma unroll
        for (int f = 0; f < 16; f++) y[f] = 0.f;
        #pragma unroll
        for (int j = 0; j < 32; j++) {
            float xj = xv[j];
            #pragma unroll
            for (int f = 0; f < 16; f++)
                y[f] += xj * sW[r * 512 + j * 16 + f];
        }
        float* hp = &g_h1[(size_t)(r * NN + n) * 16];
        float* mp = &g_m [(size_t)(r * NN + n) * 16];
        #pragma unroll
        for (int f = 0; f < 16; f += 4) {
            *(float4*)(hp + f) = make_float4(a*y[f], a*y[f+1], a*y[f+2], a*y[f+3]);
            *(float4*)(mp + f) = make_float4(0.f, 0.f, 0.f, 0.f);
        }
    }
}

// ---- layer 1 scatter on SORTED edges: 4 lanes/edge, warp-merge runs via ----
// ---- shfl segmented suffix-sum, only run-head lanes issue RED.128       ----
__global__ void k_scatter16(int Etot) {
    long long t = (long long)blockIdx.x * blockDim.x + threadIdx.x;
    int lane = threadIdx.x & 31;
    long long e = t >> 2;
    int c = (int)(t & 3);
    bool act = (e < (long long)Etot);
    int2 ed = act ? *(const int2*)&g_sorted[e] : make_int2(0, -1);
    float4 v = make_float4(0.f, 0.f, 0.f, 0.f);
    if (act) v = __ldg((const float4*)&g_h1[(size_t)ed.x * 16] + c);
    int d = ed.y;
    // segmented suffix-sum over the 8 edges in this warp (keys sorted)
    #pragma unroll
    for (int off = 4; off <= 16; off <<= 1) {
        int   nd  = __shfl_down_sync(0xffffffffu, d,   off);
        float nvx = __shfl_down_sync(0xffffffffu, v.x, off);
        float nvy = __shfl_down_sync(0xffffffffu, v.y, off);
        float nvz = __shfl_down_sync(0xffffffffu, v.z, off);
        float nvw = __shfl_down_sync(0xffffffffu, v.w, off);
        if (lane + off < 32 && nd == d) {
            v.x += nvx; v.y += nvy; v.z += nvz; v.w += nvw;
        }
    }
    int pd = __shfl_up_sync(0xffffffffu, d, 4);
    bool head = (lane < 4) || (pd != d);
    if (act && head) {
        float* mp = &g_m[(size_t)d * 16 + c * 4];
        asm volatile("red.global.add.v4.f32 [%0], {%1, %2, %3, %4};"
                     :: "l"(mp), "f"(v.x), "f"(v.y), "f"(v.z), "f"(v.w) : "memory");
    }
}

// ---------------- combine + relu + layer-2 node transform (zero g_o2) -------
__global__ void k_combine(const float* __restrict__ b1, const float* __restrict__ W2) {
    __shared__ float sW2[48], sb1[48];
    if (threadIdx.x < 48) {
        sW2[threadIdx.x] = W2[threadIdx.x];
        sb1[threadIdx.x] = b1[threadIdx.x];
    }
    __syncthreads();
    int n = blockIdx.x * blockDim.x + threadIdx.x;
    if (n >= NN) return;
    float acc[16];
    #pragma unroll
    for (int f = 0; f < 16; f++) acc[f] = 0.f;
    #pragma unroll
    for (int r = 0; r < 3; r++) {
        float ain = rs_of(g_din[r * NN + n]);
        const float* mp = &g_m[(size_t)(r * NN + n) * 16];
        #pragma unroll
        for (int f = 0; f < 16; f += 4) {
            float4 v = *(const float4*)(mp + f);
            acc[f]   += v.x * ain + sb1[r*16 + f];
            acc[f+1] += v.y * ain + sb1[r*16 + f + 1];
            acc[f+2] += v.z * ain + sb1[r*16 + f + 2];
            acc[f+3] += v.w * ain + sb1[r*16 + f + 3];
        }
    }
    #pragma unroll
    for (int f = 0; f < 16; f++) acc[f] = fmaxf(acc[f], 0.f);
    #pragma unroll
    for (int r = 0; r < 3; r++) {
        float aout = rs_of(g_dout[r * NN + n]);
        float dot = 0.f;
        #pragma unroll
        for (int f = 0; f < 16; f++) dot += acc[f] * sW2[r*16 + f];
        g_s [r * NN + n] = aout * dot;
        g_o2[r * NN + n] = 0.f;
    }
}

// ---- layer 2 scatter on SORTED edges: warp segmented suffix-sum, heads -----
__global__ void k_scatter1(int Etot) {
    int e = blockIdx.x * blockDim.x + threadIdx.x;
    int lane = threadIdx.x & 31;
    bool act = (e < Etot);
    int2 ed = act ? __ldg((const int2*)&g_sorted[e]) : make_int2(0, -1);
    float v = act ? __ldg(&g_s[ed.x]) : 0.f;
    int d = ed.y;
    #pragma unroll
    for (int off = 1; off <= 16; off <<= 1) {
        int   nd = __shfl_down_sync(0xffffffffu, d, off);
        float nv = __shfl_down_sync(0xffffffffu, v, off);
        if (lane + off < 32 && nd == d) v += nv;
    }
    int pd = __shfl_up_sync(0xffffffffu, d, 1);
    bool head = (lane == 0) || (pd != d);
    if (act && head)
        atomicAdd(&g_o2[d], v);
}

// ---------------- final ----------------
__global__ void k_final(float* __restrict__ out, const float* __restrict__ b2) {
    int n = blockIdx.x * blockDim.x + threadIdx.x;
    if (n >= NN) return;
    float o = __ldg(b2) + __ldg(b2 + 1) + __ldg(b2 + 2);
    #pragma unroll
    for (int r = 0; r < 3; r++)
        o += g_o2[r * NN + n] * rs_of(g_din[r * NN + n]);
    out[n] = o;
}

// ---------------- host ----------------
extern "C" void kernel_launch(void* const* d_in, const int* in_sizes, int n_in,
                              void* d_out, int out_size) {
    const float* x  = (const float*)d_in[0];
    const void*  src[3] = { d_in[1], d_in[3], d_in[5] };
    const void*  dst[3] = { d_in[2], d_in[4], d_in[6] };
    int          E[3]   = { in_sizes[1], in_sizes[3], in_sizes[5] };
    const float* W1 = (const float*)d_in[7];
    const float* b1 = (const float*)d_in[8];
    const float* W2 = (const float*)d_in[9];
    const float* b2 = (const float*)d_in[10];
    float*       out = (float*)d_out;

    int Etot = E[0] + E[1] + E[2];
    if (Etot > EMAX) Etot = EMAX;

    int nprobe = E[0] < 2048 ? E[0] : 2048;
    k_detect<<<1, NT>>>((const unsigned*)d_in[1], nprobe);

    k_zero<<<(NSEG + NT - 1) / NT, NT>>>();
    int eoff = 0;
    for (int r = 0; r < 3; r++) {
        k_degc<<<(E[r] + NT - 1) / NT, NT>>>(src[r], dst[r], E[r], r, eoff);
        eoff += E[r];
    }

    int nblk = (NSEG + SCAN_BS - 1) / SCAN_BS;   // 147
    k_scan1<<<nblk, SCAN_BS>>>();
    k_scan2<<<1, 256>>>(nblk);
    k_scan3<<<nblk, SCAN_BS>>>();
    k_fill<<<(Etot + NT - 1) / NT, NT>>>(Etot);

    k_layer1_node<<<(NN + NT - 1) / NT, NT>>>(x, W1);
    {
        long long work = (long long)Etot * 4;
        int blocks = (int)((work + NT - 1) / NT);
        k_scatter16<<<blocks, NT>>>(Etot);
    }

    k_combine<<<(NN + NT - 1) / NT, NT>>>(b1, W2);
    k_scatter1<<<(Etot + NT - 1) / NT, NT>>>(Etot);

    k_final<<<(NN + NT - 1) / NT, NT>>>(out, b2);
}